// round 6
// baseline (speedup 1.0000x reference)
#include <cuda_runtime.h>
#include <cuda_bf16.h>
#include <cstdint>
#include <cstddef>

#define Bn 64
#define Tn 2048
#define In 128
#define Hn 256
#define Cn 64
#define G3 768
#define SSTR 68

// ---------------- scratch ----------------
__device__ float g_gates[(size_t)Tn * G3 * Bn];   // [T][768][B]
__device__ float g_h[(size_t)Tn * Hn * Bn];       // [T][256][B]
__device__ unsigned g_bar_arrive;
__device__ unsigned g_bar_gen;

// ---------------- GEMM: C = A @ W^T + bias ----------------
// m-tile = one t covering all 64 batch rows.
// A_MODE 0: A row-major [B][T][K];  A_MODE 1: A scratch [T][K][B]
// C_MODE 0: C scratch [T][N][B];    C_MODE 1: C output  [B][T][N]
template<int A_MODE, int C_MODE>
__global__ void __launch_bounds__(256) gemm_k(
    const float* __restrict__ A, const float* __restrict__ W,
    const float* __restrict__ bias, float* __restrict__ C,
    int K, int N)
{
    __shared__ float As[16 * SSTR];  // As[k][b]
    __shared__ float Ws[16 * SSTR];  // Ws[k][n]
    const int t   = blockIdx.y;
    const int bn  = blockIdx.x * 64;
    const int tid = threadIdx.x;
    const int tx  = tid & 15;
    const int ty  = tid >> 4;
    float acc[4][4] = {};

    for (int k0 = 0; k0 < K; k0 += 16) {
        if (A_MODE == 0) {
            int bb = tid & 63, kq = (tid >> 6) << 2;
            const float4 v = *reinterpret_cast<const float4*>(
                A + ((size_t)bb * Tn + t) * K + k0 + kq);
            As[(kq + 0) * SSTR + bb] = v.x;
            As[(kq + 1) * SSTR + bb] = v.y;
            As[(kq + 2) * SSTR + bb] = v.z;
            As[(kq + 3) * SSTR + bb] = v.w;
        } else {
            int b4 = (tid & 15) << 2, kk = tid >> 4;
            const float4 v = *reinterpret_cast<const float4*>(
                A + ((size_t)t * K + k0 + kk) * Bn + b4);
            As[kk * SSTR + b4 + 0] = v.x;
            As[kk * SSTR + b4 + 1] = v.y;
            As[kk * SSTR + b4 + 2] = v.z;
            As[kk * SSTR + b4 + 3] = v.w;
        }
        {
            int nn = tid & 63, kq = (tid >> 6) << 2;
            const float4 v = *reinterpret_cast<const float4*>(
                W + (size_t)(bn + nn) * K + k0 + kq);
            Ws[(kq + 0) * SSTR + nn] = v.x;
            Ws[(kq + 1) * SSTR + nn] = v.y;
            Ws[(kq + 2) * SSTR + nn] = v.z;
            Ws[(kq + 3) * SSTR + nn] = v.w;
        }
        __syncthreads();
        #pragma unroll
        for (int k = 0; k < 16; k++) {
            float4 a = *reinterpret_cast<const float4*>(&As[k * SSTR + (ty << 2)]);
            float4 w = *reinterpret_cast<const float4*>(&Ws[k * SSTR + (tx << 2)]);
            acc[0][0] = fmaf(a.x, w.x, acc[0][0]);
            acc[0][1] = fmaf(a.x, w.y, acc[0][1]);
            acc[0][2] = fmaf(a.x, w.z, acc[0][2]);
            acc[0][3] = fmaf(a.x, w.w, acc[0][3]);
            acc[1][0] = fmaf(a.y, w.x, acc[1][0]);
            acc[1][1] = fmaf(a.y, w.y, acc[1][1]);
            acc[1][2] = fmaf(a.y, w.z, acc[1][2]);
            acc[1][3] = fmaf(a.y, w.w, acc[1][3]);
            acc[2][0] = fmaf(a.z, w.x, acc[2][0]);
            acc[2][1] = fmaf(a.z, w.y, acc[2][1]);
            acc[2][2] = fmaf(a.z, w.z, acc[2][2]);
            acc[2][3] = fmaf(a.z, w.w, acc[2][3]);
            acc[3][0] = fmaf(a.w, w.x, acc[3][0]);
            acc[3][1] = fmaf(a.w, w.y, acc[3][1]);
            acc[3][2] = fmaf(a.w, w.z, acc[3][2]);
            acc[3][3] = fmaf(a.w, w.w, acc[3][3]);
        }
        __syncthreads();
    }

    if (C_MODE == 0) {
        #pragma unroll
        for (int j = 0; j < 4; j++) {
            int n = bn + (tx << 2) + j;
            float bv = bias[n];
            float4 o = make_float4(acc[0][j] + bv, acc[1][j] + bv,
                                   acc[2][j] + bv, acc[3][j] + bv);
            *reinterpret_cast<float4*>(C + ((size_t)t * N + n) * Bn + (ty << 2)) = o;
        }
    } else {
        #pragma unroll
        for (int i = 0; i < 4; i++) {
            int bb = (ty << 2) + i;
            float4 o = make_float4(acc[i][0] + bias[bn + (tx << 2) + 0],
                                   acc[i][1] + bias[bn + (tx << 2) + 1],
                                   acc[i][2] + bias[bn + (tx << 2) + 2],
                                   acc[i][3] + bias[bn + (tx << 2) + 3]);
            *reinterpret_cast<float4*>(C + ((size_t)bb * Tn + t) * N + bn + (tx << 2)) = o;
        }
    }
}

// ---------------- grid-wide sense-reversing barrier ----------------
__device__ __forceinline__ void grid_barrier(unsigned nblk) {
    __threadfence();
    __syncthreads();
    if (threadIdx.x == 0) {
        volatile unsigned* vgen = &g_bar_gen;
        unsigned gen = *vgen;
        if (atomicAdd(&g_bar_arrive, 1u) == nblk - 1u) {
            atomicExch(&g_bar_arrive, 0u);
            __threadfence();
            atomicExch(&g_bar_gen, gen + 1u);
        } else {
            while (*vgen == gen) { }
        }
    }
    __syncthreads();
}

// ---------------- GRU recurrent scan ----------------
// 128 persistent blocks; block i owns hidden units {2i, 2i+1}.
// Thread layout: b = tid&63, u = (tid>>6)&1, kh = tid>>7 (k-half).
__global__ void __launch_bounds__(256, 1) gru_scan(
    const float* __restrict__ W_hh, const float* __restrict__ b_hh)
{
    extern __shared__ float hs[];            // [256][64] = 64 KB
    __shared__ float Ws[6 * 256];            // [gate*2+u][k]
    __shared__ float red[3 * 128];
    const int tid = threadIdx.x;
    const int b   = tid & 63;
    const int u   = (tid >> 6) & 1;
    const int kh  = tid >> 7;
    const int ug  = (blockIdx.x << 1) | u;

    for (int i = tid; i < 6 * 256; i += 256) {
        int row = i >> 8;                    // 0..5 = gate*2 + uu
        int k   = i & 255;
        int g   = row >> 1;
        int uu  = row & 1;
        Ws[i] = W_hh[((size_t)(g * Hn) + ((blockIdx.x << 1) | uu)) * Hn + k];
    }
    float br = 0.f, bz = 0.f, bn2 = 0.f;
    if (kh == 0) {
        br  = b_hh[ug];
        bz  = b_hh[Hn + ug];
        bn2 = b_hh[2 * Hn + ug];
    }
    const float* Wr = &Ws[(0 * 2 + u) * 256];
    const float* Wz = &Ws[(1 * 2 + u) * 256];
    const float* Wn = &Ws[(2 * 2 + u) * 256];
    __syncthreads();

    for (int t = 0; t < Tn; t++) {
        // stage h_{t-1} into smem ([k][b], direct copy, coalesced & conflict-free)
        if (t == 0) {
            float4 z4 = make_float4(0.f, 0.f, 0.f, 0.f);
            for (int i = tid; i < (Hn * Bn) / 4; i += 256)
                reinterpret_cast<float4*>(hs)[i] = z4;
        } else {
            const float4* src = reinterpret_cast<const float4*>(
                g_h + (size_t)(t - 1) * Hn * Bn);
            for (int i = tid; i < (Hn * Bn) / 4; i += 256) {
                float4 v;
                asm volatile("ld.global.cg.v4.f32 {%0,%1,%2,%3}, [%4];"
                             : "=f"(v.x), "=f"(v.y), "=f"(v.z), "=f"(v.w)
                             : "l"(src + i));
                reinterpret_cast<float4*>(hs)[i] = v;
            }
        }
        __syncthreads();

        float sr = 0.f, sz = 0.f, sn = 0.f;
        const int k0 = kh << 7;
        #pragma unroll 8
        for (int k = k0; k < k0 + 128; k += 4) {
            float4 wr = *reinterpret_cast<const float4*>(&Wr[k]);
            float4 wz = *reinterpret_cast<const float4*>(&Wz[k]);
            float4 wn = *reinterpret_cast<const float4*>(&Wn[k]);
            float h0 = hs[((k + 0) << 6) + b];
            float h1 = hs[((k + 1) << 6) + b];
            float h2 = hs[((k + 2) << 6) + b];
            float h3 = hs[((k + 3) << 6) + b];
            sr = fmaf(wr.x, h0, sr); sz = fmaf(wz.x, h0, sz); sn = fmaf(wn.x, h0, sn);
            sr = fmaf(wr.y, h1, sr); sz = fmaf(wz.y, h1, sz); sn = fmaf(wn.y, h1, sn);
            sr = fmaf(wr.z, h2, sr); sz = fmaf(wz.z, h2, sz); sn = fmaf(wn.z, h2, sn);
            sr = fmaf(wr.w, h3, sr); sz = fmaf(wz.w, h3, sz); sn = fmaf(wn.w, h3, sn);
        }
        if (kh == 1) {
            int idx = (u << 6) + b;
            red[idx] = sr; red[128 + idx] = sz; red[256 + idx] = sn;
        }
        __syncthreads();
        if (kh == 0) {
            int idx = (u << 6) + b;
            const size_t gbase = ((size_t)t * G3 + ug) * Bn + b;
            float xr = g_gates[gbase];
            float xz = g_gates[gbase + (size_t)Hn * Bn];
            float xz2 = g_gates[gbase + (size_t)2 * Hn * Bn];
            sr += red[idx] + br;
            sz += red[128 + idx] + bz;
            sn += red[256 + idx] + bn2;
            float r = 1.f / (1.f + __expf(-(xr + sr)));
            float z = 1.f / (1.f + __expf(-(xz + sz)));
            float n = tanhf(xz2 + r * sn);
            float hp = hs[(ug << 6) + b];
            float hnew = (1.f - z) * n + z * hp;
            g_h[((size_t)t * Hn + ug) * Bn + b] = hnew;
        }
        grid_barrier(gridDim.x);
    }
}

// ---------------- launch ----------------
extern "C" void kernel_launch(void* const* d_in, const int* in_sizes, int n_in,
                              void* d_out, int out_size) {
    const float* x     = (const float*)d_in[0];
    const float* W_ih0 = (const float*)d_in[1];
    const float* W_hh0 = (const float*)d_in[2];
    const float* b_ih0 = (const float*)d_in[3];
    const float* b_hh0 = (const float*)d_in[4];
    const float* W_ih1 = (const float*)d_in[5];
    const float* W_hh1 = (const float*)d_in[6];
    const float* b_ih1 = (const float*)d_in[7];
    const float* b_hh1 = (const float*)d_in[8];
    const float* fc_w  = (const float*)d_in[9];
    const float* fc_b  = (const float*)d_in[10];
    float* out = (float*)d_out;

    float* gates_ptr = nullptr;
    float* h_ptr = nullptr;
    cudaGetSymbolAddress((void**)&gates_ptr, g_gates);
    cudaGetSymbolAddress((void**)&h_ptr, g_h);
    cudaFuncSetAttribute(gru_scan, cudaFuncAttributeMaxDynamicSharedMemorySize,
                         Hn * Bn * (int)sizeof(float));

    // layer 0 input gates: [T][768][B] = x @ W_ih0^T + b_ih0
    gemm_k<0, 0><<<dim3(12, Tn), 256>>>(x, W_ih0, b_ih0, gates_ptr, In, G3);
    // layer 0 scan -> g_h
    gru_scan<<<128, 256, Hn * Bn * sizeof(float)>>>(W_hh0, b_hh0);
    // layer 1 input gates: g_h @ W_ih1^T + b_ih1
    gemm_k<1, 0><<<dim3(12, Tn), 256>>>(h_ptr, W_ih1, b_ih1, gates_ptr, Hn, G3);
    // layer 1 scan -> g_h (overwrites)
    gru_scan<<<128, 256, Hn * Bn * sizeof(float)>>>(W_hh1, b_hh1);
    // FC head: out[B][T][C] = g_h @ fc_w^T + fc_b
    gemm_k<1, 1><<<dim3(1, Tn), 256>>>(h_ptr, fc_w, fc_b, out, Hn, Cn);
}

// round 10
// speedup vs baseline: 2.2450x; 2.2450x over previous
#include <cuda_runtime.h>
#include <cuda_bf16.h>
#include <cstdint>
#include <cstddef>

#define Bn 64
#define Tn 2048
#define In 128
#define Hn 256
#define Cn 64
#define G3 768
#define SSTR 68

// ---------------- scratch ----------------
__device__ float g_gates[(size_t)Tn * G3 * Bn];   // [T][768][B]
__device__ float g_h[(size_t)Tn * Hn * Bn];       // [T][256][B]
__device__ unsigned g_bar_ctr;

// ---------------- GEMM: C = A @ W^T + bias ----------------
// m-tile = one t covering all 64 batch rows.
// A_MODE 0: A row-major [B][T][K];  A_MODE 1: A scratch [T][K][B]
// C_MODE 0: C scratch [T][N][B];    C_MODE 1: C output  [B][T][N]
template<int A_MODE, int C_MODE>
__global__ void __launch_bounds__(256) gemm_k(
    const float* __restrict__ A, const float* __restrict__ W,
    const float* __restrict__ bias, float* __restrict__ C,
    int K, int N)
{
    __shared__ float As[16 * SSTR];  // As[k][b]
    __shared__ float Ws[16 * SSTR];  // Ws[k][n]
    const int t   = blockIdx.y;
    const int bn  = blockIdx.x * 64;
    const int tid = threadIdx.x;
    const int tx  = tid & 15;
    const int ty  = tid >> 4;
    float acc[4][4] = {};

    for (int k0 = 0; k0 < K; k0 += 16) {
        if (A_MODE == 0) {
            int bb = tid & 63, kq = (tid >> 6) << 2;
            const float4 v = *reinterpret_cast<const float4*>(
                A + ((size_t)bb * Tn + t) * K + k0 + kq);
            As[(kq + 0) * SSTR + bb] = v.x;
            As[(kq + 1) * SSTR + bb] = v.y;
            As[(kq + 2) * SSTR + bb] = v.z;
            As[(kq + 3) * SSTR + bb] = v.w;
        } else {
            int b4 = (tid & 15) << 2, kk = tid >> 4;
            const float4 v = *reinterpret_cast<const float4*>(
                A + ((size_t)t * K + k0 + kk) * Bn + b4);
            As[kk * SSTR + b4 + 0] = v.x;
            As[kk * SSTR + b4 + 1] = v.y;
            As[kk * SSTR + b4 + 2] = v.z;
            As[kk * SSTR + b4 + 3] = v.w;
        }
        {
            int nn = tid & 63, kq = (tid >> 6) << 2;
            const float4 v = *reinterpret_cast<const float4*>(
                W + (size_t)(bn + nn) * K + k0 + kq);
            Ws[(kq + 0) * SSTR + nn] = v.x;
            Ws[(kq + 1) * SSTR + nn] = v.y;
            Ws[(kq + 2) * SSTR + nn] = v.z;
            Ws[(kq + 3) * SSTR + nn] = v.w;
        }
        __syncthreads();
        #pragma unroll
        for (int k = 0; k < 16; k++) {
            float4 a = *reinterpret_cast<const float4*>(&As[k * SSTR + (ty << 2)]);
            float4 w = *reinterpret_cast<const float4*>(&Ws[k * SSTR + (tx << 2)]);
            acc[0][0] = fmaf(a.x, w.x, acc[0][0]);
            acc[0][1] = fmaf(a.x, w.y, acc[0][1]);
            acc[0][2] = fmaf(a.x, w.z, acc[0][2]);
            acc[0][3] = fmaf(a.x, w.w, acc[0][3]);
            acc[1][0] = fmaf(a.y, w.x, acc[1][0]);
            acc[1][1] = fmaf(a.y, w.y, acc[1][1]);
            acc[1][2] = fmaf(a.y, w.z, acc[1][2]);
            acc[1][3] = fmaf(a.y, w.w, acc[1][3]);
            acc[2][0] = fmaf(a.z, w.x, acc[2][0]);
            acc[2][1] = fmaf(a.z, w.y, acc[2][1]);
            acc[2][2] = fmaf(a.z, w.z, acc[2][2]);
            acc[2][3] = fmaf(a.z, w.w, acc[2][3]);
            acc[3][0] = fmaf(a.w, w.x, acc[3][0]);
            acc[3][1] = fmaf(a.w, w.y, acc[3][1]);
            acc[3][2] = fmaf(a.w, w.z, acc[3][2]);
            acc[3][3] = fmaf(a.w, w.w, acc[3][3]);
        }
        __syncthreads();
    }

    if (C_MODE == 0) {
        #pragma unroll
        for (int j = 0; j < 4; j++) {
            int n = bn + (tx << 2) + j;
            float bv = bias[n];
            float4 o = make_float4(acc[0][j] + bv, acc[1][j] + bv,
                                   acc[2][j] + bv, acc[3][j] + bv);
            *reinterpret_cast<float4*>(C + ((size_t)t * N + n) * Bn + (ty << 2)) = o;
        }
    } else {
        #pragma unroll
        for (int i = 0; i < 4; i++) {
            int bb = (ty << 2) + i;
            float4 o = make_float4(acc[i][0] + bias[bn + (tx << 2) + 0],
                                   acc[i][1] + bias[bn + (tx << 2) + 1],
                                   acc[i][2] + bias[bn + (tx << 2) + 2],
                                   acc[i][3] + bias[bn + (tx << 2) + 3]);
            *reinterpret_cast<float4*>(C + ((size_t)bb * Tn + t) * N + bn + (tx << 2)) = o;
        }
    }
}

// ---------------- GRU recurrent scan ----------------
// 128 persistent CTAs; CTA p owns hidden units {2p, 2p+1}.
// Thread (b = tid&63, kq = tid>>6): computes the kq-th quarter (64 k) of all
// 6 recurrent dot products (2 units x 3 gates) for batch b. h is read
// directly from L2 (__ldcg) -- no smem restage, each h value read once/CTA.
// Cross-quarter reduction via smem; kq==0 threads run the gate epilogue.
__global__ void __launch_bounds__(256, 1) gru_scan(
    const float* __restrict__ W_hh, const float* __restrict__ b_hh,
    const float* __restrict__ gates, float* __restrict__ hseq)
{
    __shared__ float Ws[6 * 256];        // [j][k], j = gate*2 + unit
    __shared__ float red[3 * 6 * 64];    // [kq-1][j][b]
    const int tid = threadIdx.x;
    const int b   = tid & 63;
    const int kq  = tid >> 6;            // 0..3
    const int p   = blockIdx.x;          // unit pair index
    const int k0  = kq << 6;

    // Load the 6 W_hh rows for this CTA's two units.
    for (int i = tid; i < 6 * 256; i += 256) {
        int j = i >> 8, k = i & 255;
        int g = j >> 1, uu = j & 1;
        Ws[i] = W_hh[((size_t)(g * Hn) + (2 * p + uu)) * Hn + k];
    }
    float bias[6];
    if (kq == 0) {
        #pragma unroll
        for (int j = 0; j < 6; j++)
            bias[j] = b_hh[(j >> 1) * Hn + 2 * p + (j & 1)];
    }
    __syncthreads();

    unsigned target = 0;
    for (int t = 0; t < Tn; t++) {
        // -- prefetch x-side gate pre-activations (DRAM) + own-unit h_prev --
        float xg[6];
        float hprev0 = 0.f, hprev1 = 0.f;
        if (kq == 0) {
            const float* gp = gates + (size_t)t * G3 * Bn + b;
            #pragma unroll
            for (int j = 0; j < 6; j++) {
                int g = j >> 1, uu = j & 1;
                xg[j] = __ldg(gp + (size_t)(g * Hn + 2 * p + uu) * Bn);
            }
            if (t > 0) {
                const float* hb = hseq + (size_t)(t - 1) * Hn * Bn + b;
                hprev0 = __ldcg(hb + (size_t)(2 * p + 0) * Bn);
                hprev1 = __ldcg(hb + (size_t)(2 * p + 1) * Bn);
            }
        }

        // -- 6 partial dot products over this thread's k-quarter --
        float a0 = 0.f, a1 = 0.f, a2 = 0.f, a3 = 0.f, a4 = 0.f, a5 = 0.f;
        if (t > 0) {
            const float* hp = hseq + ((size_t)(t - 1) * Hn + k0) * Bn + b;
            #pragma unroll
            for (int kk = 0; kk < 64; kk += 4) {
                float h0 = __ldcg(hp + (size_t)(kk + 0) * Bn);
                float h1 = __ldcg(hp + (size_t)(kk + 1) * Bn);
                float h2 = __ldcg(hp + (size_t)(kk + 2) * Bn);
                float h3 = __ldcg(hp + (size_t)(kk + 3) * Bn);
                float4 w0 = *reinterpret_cast<const float4*>(&Ws[0 * 256 + k0 + kk]);
                float4 w1 = *reinterpret_cast<const float4*>(&Ws[1 * 256 + k0 + kk]);
                float4 w2 = *reinterpret_cast<const float4*>(&Ws[2 * 256 + k0 + kk]);
                float4 w3 = *reinterpret_cast<const float4*>(&Ws[3 * 256 + k0 + kk]);
                float4 w4 = *reinterpret_cast<const float4*>(&Ws[4 * 256 + k0 + kk]);
                float4 w5 = *reinterpret_cast<const float4*>(&Ws[5 * 256 + k0 + kk]);
                a0 = fmaf(w0.x, h0, a0); a1 = fmaf(w1.x, h0, a1); a2 = fmaf(w2.x, h0, a2);
                a3 = fmaf(w3.x, h0, a3); a4 = fmaf(w4.x, h0, a4); a5 = fmaf(w5.x, h0, a5);
                a0 = fmaf(w0.y, h1, a0); a1 = fmaf(w1.y, h1, a1); a2 = fmaf(w2.y, h1, a2);
                a3 = fmaf(w3.y, h1, a3); a4 = fmaf(w4.y, h1, a4); a5 = fmaf(w5.y, h1, a5);
                a0 = fmaf(w0.z, h2, a0); a1 = fmaf(w1.z, h2, a1); a2 = fmaf(w2.z, h2, a2);
                a3 = fmaf(w3.z, h2, a3); a4 = fmaf(w4.z, h2, a4); a5 = fmaf(w5.z, h2, a5);
                a0 = fmaf(w0.w, h3, a0); a1 = fmaf(w1.w, h3, a1); a2 = fmaf(w2.w, h3, a2);
                a3 = fmaf(w3.w, h3, a3); a4 = fmaf(w4.w, h3, a4); a5 = fmaf(w5.w, h3, a5);
            }
        }

        // -- cross-quarter reduction --
        if (kq != 0) {
            float* rp = &red[(kq - 1) * 6 * 64 + b];
            rp[0 * 64] = a0; rp[1 * 64] = a1; rp[2 * 64] = a2;
            rp[3 * 64] = a3; rp[4 * 64] = a4; rp[5 * 64] = a5;
        }
        __syncthreads();

        if (kq == 0) {
            float acc[6] = {a0, a1, a2, a3, a4, a5};
            #pragma unroll
            for (int j = 0; j < 6; j++)
                acc[j] += red[0 * 384 + j * 64 + b]
                        + red[1 * 384 + j * 64 + b]
                        + red[2 * 384 + j * 64 + b] + bias[j];
            float* ho = hseq + (size_t)t * Hn * Bn + b;
            #pragma unroll
            for (int uu = 0; uu < 2; uu++) {
                float r = 1.f / (1.f + __expf(-(xg[0 + uu] + acc[0 + uu])));
                float z = 1.f / (1.f + __expf(-(xg[2 + uu] + acc[2 + uu])));
                float nv = tanhf(xg[4 + uu] + r * acc[4 + uu]);
                float hp = uu ? hprev1 : hprev0;
                float hn = (1.f - z) * nv + z * hp;
                __stcg(ho + (size_t)(2 * p + uu) * Bn, hn);
            }
        }
        __syncthreads();

        // -- grid barrier: release arrive on monotonic counter, acquire spin --
        target += gridDim.x;
        if (tid == 0) {
            asm volatile("red.release.gpu.global.add.u32 [%0], 1;"
                         :: "l"(&g_bar_ctr) : "memory");
            unsigned v;
            do {
                asm volatile("ld.acquire.gpu.global.u32 %0, [%1];"
                             : "=r"(v) : "l"(&g_bar_ctr));
            } while (v < target);
        }
        __syncthreads();
    }
}

// ---------------- launch ----------------
extern "C" void kernel_launch(void* const* d_in, const int* in_sizes, int n_in,
                              void* d_out, int out_size) {
    const float* x     = (const float*)d_in[0];
    const float* W_ih0 = (const float*)d_in[1];
    const float* W_hh0 = (const float*)d_in[2];
    const float* b_ih0 = (const float*)d_in[3];
    const float* b_hh0 = (const float*)d_in[4];
    const float* W_ih1 = (const float*)d_in[5];
    const float* W_hh1 = (const float*)d_in[6];
    const float* b_ih1 = (const float*)d_in[7];
    const float* b_hh1 = (const float*)d_in[8];
    const float* fc_w  = (const float*)d_in[9];
    const float* fc_b  = (const float*)d_in[10];
    float* out = (float*)d_out;

    float* gates_ptr = nullptr;
    float* h_ptr = nullptr;
    unsigned* bar_ptr = nullptr;
    cudaGetSymbolAddress((void**)&gates_ptr, g_gates);
    cudaGetSymbolAddress((void**)&h_ptr, g_h);
    cudaGetSymbolAddress((void**)&bar_ptr, g_bar_ctr);

    // layer 0 input gates: [T][768][B] = x @ W_ih0^T + b_ih0
    gemm_k<0, 0><<<dim3(12, Tn), 256>>>(x, W_ih0, b_ih0, gates_ptr, In, G3);
    // layer 0 scan -> g_h
    cudaMemsetAsync(bar_ptr, 0, sizeof(unsigned));
    gru_scan<<<128, 256>>>(W_hh0, b_hh0, gates_ptr, h_ptr);
    // layer 1 input gates: g_h @ W_ih1^T + b_ih1
    gemm_k<1, 0><<<dim3(12, Tn), 256>>>(h_ptr, W_ih1, b_ih1, gates_ptr, Hn, G3);
    // layer 1 scan -> g_h (overwrites)
    cudaMemsetAsync(bar_ptr, 0, sizeof(unsigned));
    gru_scan<<<128, 256>>>(W_hh1, b_hh1, gates_ptr, h_ptr);
    // FC head: out[B][T][C] = g_h @ fc_w^T + fc_b
    gemm_k<1, 1><<<dim3(1, Tn), 256>>>(h_ptr, fc_w, fc_b, out, Hn, Cn);
}

// round 12
// speedup vs baseline: 2.2565x; 1.0052x over previous
#include <cuda_runtime.h>
#include <cuda_bf16.h>
#include <cstdint>
#include <cstddef>

#define Bn 64
#define Tn 2048
#define In 128
#define Hn 256
#define Cn 64
#define G3 768
#define SSTR 68

// ---------------- scratch ----------------
__device__ float g_gates[(size_t)Tn * G3 * Bn];   // [T][768][B]
__device__ float g_h[(size_t)Tn * Hn * Bn];       // [T][256][B]
__device__ unsigned g_bar_ctr;

// ---------------- GEMM: C = A @ W^T + bias ----------------
// m-tile = one t covering all 64 batch rows.
// A_MODE 0: A row-major [B][T][K];  A_MODE 1: A scratch [T][K][B]
// C_MODE 0: C scratch [T][N][B];    C_MODE 1: C output  [B][T][N]
template<int A_MODE, int C_MODE>
__global__ void __launch_bounds__(256) gemm_k(
    const float* __restrict__ A, const float* __restrict__ W,
    const float* __restrict__ bias, float* __restrict__ C,
    int K, int N)
{
    __shared__ float As[16 * SSTR];  // As[k][b]
    __shared__ float Ws[16 * SSTR];  // Ws[k][n]
    const int t   = blockIdx.y;
    const int bn  = blockIdx.x * 64;
    const int tid = threadIdx.x;
    const int tx  = tid & 15;
    const int ty  = tid >> 4;
    float acc[4][4] = {};

    for (int k0 = 0; k0 < K; k0 += 16) {
        if (A_MODE == 0) {
            int bb = tid & 63, kq = (tid >> 6) << 2;
            const float4 v = *reinterpret_cast<const float4*>(
                A + ((size_t)bb * Tn + t) * K + k0 + kq);
            As[(kq + 0) * SSTR + bb] = v.x;
            As[(kq + 1) * SSTR + bb] = v.y;
            As[(kq + 2) * SSTR + bb] = v.z;
            As[(kq + 3) * SSTR + bb] = v.w;
        } else {
            int b4 = (tid & 15) << 2, kk = tid >> 4;
            const float4 v = *reinterpret_cast<const float4*>(
                A + ((size_t)t * K + k0 + kk) * Bn + b4);
            As[kk * SSTR + b4 + 0] = v.x;
            As[kk * SSTR + b4 + 1] = v.y;
            As[kk * SSTR + b4 + 2] = v.z;
            As[kk * SSTR + b4 + 3] = v.w;
        }
        {
            int nn = tid & 63, kq = (tid >> 6) << 2;
            const float4 v = *reinterpret_cast<const float4*>(
                W + (size_t)(bn + nn) * K + k0 + kq);
            Ws[(kq + 0) * SSTR + nn] = v.x;
            Ws[(kq + 1) * SSTR + nn] = v.y;
            Ws[(kq + 2) * SSTR + nn] = v.z;
            Ws[(kq + 3) * SSTR + nn] = v.w;
        }
        __syncthreads();
        #pragma unroll
        for (int k = 0; k < 16; k++) {
            float4 a = *reinterpret_cast<const float4*>(&As[k * SSTR + (ty << 2)]);
            float4 w = *reinterpret_cast<const float4*>(&Ws[k * SSTR + (tx << 2)]);
            acc[0][0] = fmaf(a.x, w.x, acc[0][0]);
            acc[0][1] = fmaf(a.x, w.y, acc[0][1]);
            acc[0][2] = fmaf(a.x, w.z, acc[0][2]);
            acc[0][3] = fmaf(a.x, w.w, acc[0][3]);
            acc[1][0] = fmaf(a.y, w.x, acc[1][0]);
            acc[1][1] = fmaf(a.y, w.y, acc[1][1]);
            acc[1][2] = fmaf(a.y, w.z, acc[1][2]);
            acc[1][3] = fmaf(a.y, w.w, acc[1][3]);
            acc[2][0] = fmaf(a.z, w.x, acc[2][0]);
            acc[2][1] = fmaf(a.z, w.y, acc[2][1]);
            acc[2][2] = fmaf(a.z, w.z, acc[2][2]);
            acc[2][3] = fmaf(a.z, w.w, acc[2][3]);
            acc[3][0] = fmaf(a.w, w.x, acc[3][0]);
            acc[3][1] = fmaf(a.w, w.y, acc[3][1]);
            acc[3][2] = fmaf(a.w, w.z, acc[3][2]);
            acc[3][3] = fmaf(a.w, w.w, acc[3][3]);
        }
        __syncthreads();
    }

    if (C_MODE == 0) {
        #pragma unroll
        for (int j = 0; j < 4; j++) {
            int n = bn + (tx << 2) + j;
            float bv = bias[n];
            float4 o = make_float4(acc[0][j] + bv, acc[1][j] + bv,
                                   acc[2][j] + bv, acc[3][j] + bv);
            *reinterpret_cast<float4*>(C + ((size_t)t * N + n) * Bn + (ty << 2)) = o;
        }
    } else {
        #pragma unroll
        for (int i = 0; i < 4; i++) {
            int bb = (ty << 2) + i;
            float4 o = make_float4(acc[i][0] + bias[bn + (tx << 2) + 0],
                                   acc[i][1] + bias[bn + (tx << 2) + 1],
                                   acc[i][2] + bias[bn + (tx << 2) + 2],
                                   acc[i][3] + bias[bn + (tx << 2) + 3]);
            *reinterpret_cast<float4*>(C + ((size_t)bb * Tn + t) * N + bn + (tx << 2)) = o;
        }
    }
}

// ---------------- GRU recurrent scan ----------------
// 128 persistent CTAs; CTA p owns hidden units {2p, 2p+1}.
// Thread (b = tid&63, kq = tid>>6): computes the kq-th quarter (64 k) of all
// 6 recurrent dot products (2 units x 3 gates) for batch b. h is read
// directly from L2 (__ldcg) -- no smem restage, each h value read once/CTA.
// Cross-quarter reduction via smem; kq==0 threads run the gate epilogue.
__global__ void __launch_bounds__(256, 1) gru_scan(
    const float* __restrict__ W_hh, const float* __restrict__ b_hh,
    const float* __restrict__ gates, float* __restrict__ hseq)
{
    __shared__ float Ws[6 * 256];        // [j][k], j = gate*2 + unit
    __shared__ float red[3 * 6 * 64];    // [kq-1][j][b]
    const int tid = threadIdx.x;
    const int b   = tid & 63;
    const int kq  = tid >> 6;            // 0..3
    const int p   = blockIdx.x;          // unit pair index
    const int k0  = kq << 6;

    // Load the 6 W_hh rows for this CTA's two units.
    for (int i = tid; i < 6 * 256; i += 256) {
        int j = i >> 8, k = i & 255;
        int g = j >> 1, uu = j & 1;
        Ws[i] = W_hh[((size_t)(g * Hn) + (2 * p + uu)) * Hn + k];
    }
    float bias[6];
    if (kq == 0) {
        #pragma unroll
        for (int j = 0; j < 6; j++)
            bias[j] = b_hh[(j >> 1) * Hn + 2 * p + (j & 1)];
    }
    __syncthreads();

    unsigned target = 0;
    for (int t = 0; t < Tn; t++) {
        // -- prefetch x-side gate pre-activations (DRAM) + own-unit h_prev --
        float xg[6];
        float hprev0 = 0.f, hprev1 = 0.f;
        if (kq == 0) {
            const float* gp = gates + (size_t)t * G3 * Bn + b;
            #pragma unroll
            for (int j = 0; j < 6; j++) {
                int g = j >> 1, uu = j & 1;
                xg[j] = __ldg(gp + (size_t)(g * Hn + 2 * p + uu) * Bn);
            }
            if (t > 0) {
                const float* hb = hseq + (size_t)(t - 1) * Hn * Bn + b;
                hprev0 = __ldcg(hb + (size_t)(2 * p + 0) * Bn);
                hprev1 = __ldcg(hb + (size_t)(2 * p + 1) * Bn);
            }
        }

        // -- 6 partial dot products over this thread's k-quarter --
        float a0 = 0.f, a1 = 0.f, a2 = 0.f, a3 = 0.f, a4 = 0.f, a5 = 0.f;
        if (t > 0) {
            const float* hp = hseq + ((size_t)(t - 1) * Hn + k0) * Bn + b;
            #pragma unroll
            for (int kk = 0; kk < 64; kk += 4) {
                float h0 = __ldcg(hp + (size_t)(kk + 0) * Bn);
                float h1 = __ldcg(hp + (size_t)(kk + 1) * Bn);
                float h2 = __ldcg(hp + (size_t)(kk + 2) * Bn);
                float h3 = __ldcg(hp + (size_t)(kk + 3) * Bn);
                float4 w0 = *reinterpret_cast<const float4*>(&Ws[0 * 256 + k0 + kk]);
                float4 w1 = *reinterpret_cast<const float4*>(&Ws[1 * 256 + k0 + kk]);
                float4 w2 = *reinterpret_cast<const float4*>(&Ws[2 * 256 + k0 + kk]);
                float4 w3 = *reinterpret_cast<const float4*>(&Ws[3 * 256 + k0 + kk]);
                float4 w4 = *reinterpret_cast<const float4*>(&Ws[4 * 256 + k0 + kk]);
                float4 w5 = *reinterpret_cast<const float4*>(&Ws[5 * 256 + k0 + kk]);
                a0 = fmaf(w0.x, h0, a0); a1 = fmaf(w1.x, h0, a1); a2 = fmaf(w2.x, h0, a2);
                a3 = fmaf(w3.x, h0, a3); a4 = fmaf(w4.x, h0, a4); a5 = fmaf(w5.x, h0, a5);
                a0 = fmaf(w0.y, h1, a0); a1 = fmaf(w1.y, h1, a1); a2 = fmaf(w2.y, h1, a2);
                a3 = fmaf(w3.y, h1, a3); a4 = fmaf(w4.y, h1, a4); a5 = fmaf(w5.y, h1, a5);
                a0 = fmaf(w0.z, h2, a0); a1 = fmaf(w1.z, h2, a1); a2 = fmaf(w2.z, h2, a2);
                a3 = fmaf(w3.z, h2, a3); a4 = fmaf(w4.z, h2, a4); a5 = fmaf(w5.z, h2, a5);
                a0 = fmaf(w0.w, h3, a0); a1 = fmaf(w1.w, h3, a1); a2 = fmaf(w2.w, h3, a2);
                a3 = fmaf(w3.w, h3, a3); a4 = fmaf(w4.w, h3, a4); a5 = fmaf(w5.w, h3, a5);
            }
        }

        // -- cross-quarter reduction --
        if (kq != 0) {
            float* rp = &red[(kq - 1) * 6 * 64 + b];
            rp[0 * 64] = a0; rp[1 * 64] = a1; rp[2 * 64] = a2;
            rp[3 * 64] = a3; rp[4 * 64] = a4; rp[5 * 64] = a5;
        }
        __syncthreads();

        if (kq == 0) {
            float acc[6] = {a0, a1, a2, a3, a4, a5};
            #pragma unroll
            for (int j = 0; j < 6; j++)
                acc[j] += red[0 * 384 + j * 64 + b]
                        + red[1 * 384 + j * 64 + b]
                        + red[2 * 384 + j * 64 + b] + bias[j];
            float* ho = hseq + (size_t)t * Hn * Bn + b;
            #pragma unroll
            for (int uu = 0; uu < 2; uu++) {
                float r = 1.f / (1.f + __expf(-(xg[0 + uu] + acc[0 + uu])));
                float z = 1.f / (1.f + __expf(-(xg[2 + uu] + acc[2 + uu])));
                float nv = tanhf(xg[4 + uu] + r * acc[4 + uu]);
                float hp = uu ? hprev1 : hprev0;
                float hn = (1.f - z) * nv + z * hp;
                __stcg(ho + (size_t)(2 * p + uu) * Bn, hn);
            }
        }
        __syncthreads();

        // -- grid barrier: release arrive on monotonic counter, acquire spin --
        target += gridDim.x;
        if (tid == 0) {
            asm volatile("red.release.gpu.global.add.u32 [%0], 1;"
                         :: "l"(&g_bar_ctr) : "memory");
            unsigned v;
            do {
                asm volatile("ld.acquire.gpu.global.u32 %0, [%1];"
                             : "=r"(v) : "l"(&g_bar_ctr));
            } while (v < target);
        }
        __syncthreads();
    }
}

// ---------------- launch ----------------
extern "C" void kernel_launch(void* const* d_in, const int* in_sizes, int n_in,
                              void* d_out, int out_size) {
    const float* x     = (const float*)d_in[0];
    const float* W_ih0 = (const float*)d_in[1];
    const float* W_hh0 = (const float*)d_in[2];
    const float* b_ih0 = (const float*)d_in[3];
    const float* b_hh0 = (const float*)d_in[4];
    const float* W_ih1 = (const float*)d_in[5];
    const float* W_hh1 = (const float*)d_in[6];
    const float* b_ih1 = (const float*)d_in[7];
    const float* b_hh1 = (const float*)d_in[8];
    const float* fc_w  = (const float*)d_in[9];
    const float* fc_b  = (const float*)d_in[10];
    float* out = (float*)d_out;

    float* gates_ptr = nullptr;
    float* h_ptr = nullptr;
    unsigned* bar_ptr = nullptr;
    cudaGetSymbolAddress((void**)&gates_ptr, g_gates);
    cudaGetSymbolAddress((void**)&h_ptr, g_h);
    cudaGetSymbolAddress((void**)&bar_ptr, g_bar_ctr);

    // layer 0 input gates: [T][768][B] = x @ W_ih0^T + b_ih0
    gemm_k<0, 0><<<dim3(12, Tn), 256>>>(x, W_ih0, b_ih0, gates_ptr, In, G3);
    // layer 0 scan -> g_h
    cudaMemsetAsync(bar_ptr, 0, sizeof(unsigned));
    gru_scan<<<128, 256>>>(W_hh0, b_hh0, gates_ptr, h_ptr);
    // layer 1 input gates: g_h @ W_ih1^T + b_ih1
    gemm_k<1, 0><<<dim3(12, Tn), 256>>>(h_ptr, W_ih1, b_ih1, gates_ptr, Hn, G3);
    // layer 1 scan -> g_h (overwrites)
    cudaMemsetAsync(bar_ptr, 0, sizeof(unsigned));
    gru_scan<<<128, 256>>>(W_hh1, b_hh1, gates_ptr, h_ptr);
    // FC head: out[B][T][C] = g_h @ fc_w^T + fc_b
    gemm_k<1, 1><<<dim3(1, Tn), 256>>>(h_ptr, fc_w, fc_b, out, Hn, Cn);
}

// round 14
// speedup vs baseline: 2.4779x; 1.0981x over previous
#include <cuda_runtime.h>
#include <cuda_bf16.h>
#include <cstdint>
#include <cstddef>

#define Bn 64
#define Tn 2048
#define In 128
#define Hn 256
#define Cn 64
#define G3 768
#define SSTR 68

// ---------------- scratch ----------------
__device__ float g_gates[(size_t)Tn * G3 * Bn];   // [T][768][B]
__device__ float g_h[(size_t)Tn * Hn * Bn];       // [T][256][B]
__device__ unsigned g_bar_ctr;

// ---------------- GEMM: C = A @ W^T + bias ----------------
// m-tile = one t covering all 64 batch rows.
// A_MODE 0: A row-major [B][T][K];  A_MODE 1: A scratch [T][K][B]
// C_MODE 0: C scratch [T][N][B];    C_MODE 1: C output  [B][T][N]
template<int A_MODE, int C_MODE>
__global__ void __launch_bounds__(256) gemm_k(
    const float* __restrict__ A, const float* __restrict__ W,
    const float* __restrict__ bias, float* __restrict__ C,
    int K, int N)
{
    __shared__ float As[16 * SSTR];  // As[k][b]
    __shared__ float Ws[16 * SSTR];  // Ws[k][n]
    const int t   = blockIdx.y;
    const int bn  = blockIdx.x * 64;
    const int tid = threadIdx.x;
    const int tx  = tid & 15;
    const int ty  = tid >> 4;
    float acc[4][4] = {};

    for (int k0 = 0; k0 < K; k0 += 16) {
        if (A_MODE == 0) {
            int bb = tid & 63, kq = (tid >> 6) << 2;
            const float4 v = *reinterpret_cast<const float4*>(
                A + ((size_t)bb * Tn + t) * K + k0 + kq);
            As[(kq + 0) * SSTR + bb] = v.x;
            As[(kq + 1) * SSTR + bb] = v.y;
            As[(kq + 2) * SSTR + bb] = v.z;
            As[(kq + 3) * SSTR + bb] = v.w;
        } else {
            int b4 = (tid & 15) << 2, kk = tid >> 4;
            const float4 v = *reinterpret_cast<const float4*>(
                A + ((size_t)t * K + k0 + kk) * Bn + b4);
            As[kk * SSTR + b4 + 0] = v.x;
            As[kk * SSTR + b4 + 1] = v.y;
            As[kk * SSTR + b4 + 2] = v.z;
            As[kk * SSTR + b4 + 3] = v.w;
        }
        {
            int nn = tid & 63, kq = (tid >> 6) << 2;
            const float4 v = *reinterpret_cast<const float4*>(
                W + (size_t)(bn + nn) * K + k0 + kq);
            Ws[(kq + 0) * SSTR + nn] = v.x;
            Ws[(kq + 1) * SSTR + nn] = v.y;
            Ws[(kq + 2) * SSTR + nn] = v.z;
            Ws[(kq + 3) * SSTR + nn] = v.w;
        }
        __syncthreads();
        #pragma unroll
        for (int k = 0; k < 16; k++) {
            float4 a = *reinterpret_cast<const float4*>(&As[k * SSTR + (ty << 2)]);
            float4 w = *reinterpret_cast<const float4*>(&Ws[k * SSTR + (tx << 2)]);
            acc[0][0] = fmaf(a.x, w.x, acc[0][0]);
            acc[0][1] = fmaf(a.x, w.y, acc[0][1]);
            acc[0][2] = fmaf(a.x, w.z, acc[0][2]);
            acc[0][3] = fmaf(a.x, w.w, acc[0][3]);
            acc[1][0] = fmaf(a.y, w.x, acc[1][0]);
            acc[1][1] = fmaf(a.y, w.y, acc[1][1]);
            acc[1][2] = fmaf(a.y, w.z, acc[1][2]);
            acc[1][3] = fmaf(a.y, w.w, acc[1][3]);
            acc[2][0] = fmaf(a.z, w.x, acc[2][0]);
            acc[2][1] = fmaf(a.z, w.y, acc[2][1]);
            acc[2][2] = fmaf(a.z, w.z, acc[2][2]);
            acc[2][3] = fmaf(a.z, w.w, acc[2][3]);
            acc[3][0] = fmaf(a.w, w.x, acc[3][0]);
            acc[3][1] = fmaf(a.w, w.y, acc[3][1]);
            acc[3][2] = fmaf(a.w, w.z, acc[3][2]);
            acc[3][3] = fmaf(a.w, w.w, acc[3][3]);
        }
        __syncthreads();
    }

    if (C_MODE == 0) {
        #pragma unroll
        for (int j = 0; j < 4; j++) {
            int n = bn + (tx << 2) + j;
            float bv = bias[n];
            float4 o = make_float4(acc[0][j] + bv, acc[1][j] + bv,
                                   acc[2][j] + bv, acc[3][j] + bv);
            *reinterpret_cast<float4*>(C + ((size_t)t * N + n) * Bn + (ty << 2)) = o;
        }
    } else {
        #pragma unroll
        for (int i = 0; i < 4; i++) {
            int bb = (ty << 2) + i;
            float4 o = make_float4(acc[i][0] + bias[bn + (tx << 2) + 0],
                                   acc[i][1] + bias[bn + (tx << 2) + 1],
                                   acc[i][2] + bias[bn + (tx << 2) + 2],
                                   acc[i][3] + bias[bn + (tx << 2) + 3]);
            *reinterpret_cast<float4*>(C + ((size_t)bb * Tn + t) * N + bn + (tx << 2)) = o;
        }
    }
}

// ---------------- GRU recurrent scan ----------------
// 128 persistent CTAs; CTA p owns hidden units {2p, 2p+1}.
// Thread (bp = tid&31, kq = tid>>5): b-pair {2bp,2bp+1} x k-eighth (32 k),
// all 6 recurrent rows (2 units x 3 gates). h read once per CTA via float2
// LDG.cg; W from smem (broadcast); 8-way k reduction through smem; 128-thread
// (u,b) epilogue does the gate math.
__global__ void __launch_bounds__(256, 1) gru_scan(
    const float* __restrict__ W_hh, const float* __restrict__ b_hh,
    const float* __restrict__ gates, float* __restrict__ hseq)
{
    __shared__ float Ws[6 * 256];          // [j][k], j = gate*2 + unit
    __shared__ float red[8 * 6 * 64];      // [kq][j][b]  (12 KB)
    const int tid = threadIdx.x;
    const int bp  = tid & 31;              // b-pair index (b = 2bp, 2bp+1)
    const int kq  = tid >> 5;              // 0..7
    const int p   = blockIdx.x;
    const int k0  = kq << 5;               // 32 k per thread

    // Load the 6 W_hh rows for this CTA's two units.
    for (int i = tid; i < 6 * 256; i += 256) {
        int j = i >> 8, k = i & 255;
        Ws[i] = W_hh[((size_t)((j >> 1) * Hn) + (2 * p + (j & 1))) * Hn + k];
    }
    // Epilogue role: tid < 128 handles (u = tid>>6, b = tid&63).
    const int eu = tid >> 6, eb = tid & 63;
    float ebias[3];
    if (tid < 128) {
        #pragma unroll
        for (int g = 0; g < 3; g++)
            ebias[g] = b_hh[g * Hn + 2 * p + eu];
    }
    __syncthreads();

    unsigned target = 0;
    for (int t = 0; t < Tn; t++) {
        // -- prefetch x-side gate pre-activations + own h_prev (epilogue threads) --
        float xg0 = 0.f, xg1 = 0.f, xg2 = 0.f, hprev = 0.f;
        if (tid < 128) {
            const float* gp = gates + (size_t)t * G3 * Bn
                              + (size_t)(2 * p + eu) * Bn + eb;
            xg0 = __ldg(gp);
            xg1 = __ldg(gp + (size_t)Hn * Bn);
            xg2 = __ldg(gp + (size_t)2 * Hn * Bn);
            if (t > 0)
                hprev = __ldcg(hseq + ((size_t)(t - 1) * Hn + 2 * p + eu) * Bn + eb);
        }

        // -- 6 partial dot products (each over 2 b) for this k-eighth --
        float2 a0 = {0.f, 0.f}, a1 = a0, a2 = a0, a3 = a0, a4 = a0, a5 = a0;
        if (t > 0) {
            const float* hp = hseq + ((size_t)(t - 1) * Hn + k0) * Bn + (bp << 1);
            #pragma unroll
            for (int kk = 0; kk < 32; kk += 4) {
                float2 h0 = __ldcg(reinterpret_cast<const float2*>(hp + (size_t)(kk + 0) * Bn));
                float2 h1 = __ldcg(reinterpret_cast<const float2*>(hp + (size_t)(kk + 1) * Bn));
                float2 h2 = __ldcg(reinterpret_cast<const float2*>(hp + (size_t)(kk + 2) * Bn));
                float2 h3 = __ldcg(reinterpret_cast<const float2*>(hp + (size_t)(kk + 3) * Bn));
                float4 w0 = *reinterpret_cast<const float4*>(&Ws[0 * 256 + k0 + kk]);
                float4 w1 = *reinterpret_cast<const float4*>(&Ws[1 * 256 + k0 + kk]);
                float4 w2 = *reinterpret_cast<const float4*>(&Ws[2 * 256 + k0 + kk]);
                float4 w3 = *reinterpret_cast<const float4*>(&Ws[3 * 256 + k0 + kk]);
                float4 w4 = *reinterpret_cast<const float4*>(&Ws[4 * 256 + k0 + kk]);
                float4 w5 = *reinterpret_cast<const float4*>(&Ws[5 * 256 + k0 + kk]);
                a0.x = fmaf(w0.x, h0.x, a0.x); a0.y = fmaf(w0.x, h0.y, a0.y);
                a1.x = fmaf(w1.x, h0.x, a1.x); a1.y = fmaf(w1.x, h0.y, a1.y);
                a2.x = fmaf(w2.x, h0.x, a2.x); a2.y = fmaf(w2.x, h0.y, a2.y);
                a3.x = fmaf(w3.x, h0.x, a3.x); a3.y = fmaf(w3.x, h0.y, a3.y);
                a4.x = fmaf(w4.x, h0.x, a4.x); a4.y = fmaf(w4.x, h0.y, a4.y);
                a5.x = fmaf(w5.x, h0.x, a5.x); a5.y = fmaf(w5.x, h0.y, a5.y);
                a0.x = fmaf(w0.y, h1.x, a0.x); a0.y = fmaf(w0.y, h1.y, a0.y);
                a1.x = fmaf(w1.y, h1.x, a1.x); a1.y = fmaf(w1.y, h1.y, a1.y);
                a2.x = fmaf(w2.y, h1.x, a2.x); a2.y = fmaf(w2.y, h1.y, a2.y);
                a3.x = fmaf(w3.y, h1.x, a3.x); a3.y = fmaf(w3.y, h1.y, a3.y);
                a4.x = fmaf(w4.y, h1.x, a4.x); a4.y = fmaf(w4.y, h1.y, a4.y);
                a5.x = fmaf(w5.y, h1.x, a5.x); a5.y = fmaf(w5.y, h1.y, a5.y);
                a0.x = fmaf(w0.z, h2.x, a0.x); a0.y = fmaf(w0.z, h2.y, a0.y);
                a1.x = fmaf(w1.z, h2.x, a1.x); a1.y = fmaf(w1.z, h2.y, a1.y);
                a2.x = fmaf(w2.z, h2.x, a2.x); a2.y = fmaf(w2.z, h2.y, a2.y);
                a3.x = fmaf(w3.z, h2.x, a3.x); a3.y = fmaf(w3.z, h2.y, a3.y);
                a4.x = fmaf(w4.z, h2.x, a4.x); a4.y = fmaf(w4.z, h2.y, a4.y);
                a5.x = fmaf(w5.z, h2.x, a5.x); a5.y = fmaf(w5.z, h2.y, a5.y);
                a0.x = fmaf(w0.w, h3.x, a0.x); a0.y = fmaf(w0.w, h3.y, a0.y);
                a1.x = fmaf(w1.w, h3.x, a1.x); a1.y = fmaf(w1.w, h3.y, a1.y);
                a2.x = fmaf(w2.w, h3.x, a2.x); a2.y = fmaf(w2.w, h3.y, a2.y);
                a3.x = fmaf(w3.w, h3.x, a3.x); a3.y = fmaf(w3.w, h3.y, a3.y);
                a4.x = fmaf(w4.w, h3.x, a4.x); a4.y = fmaf(w4.w, h3.y, a4.y);
                a5.x = fmaf(w5.w, h3.x, a5.x); a5.y = fmaf(w5.w, h3.y, a5.y);
            }
        }

        // -- stash partials: red[kq][j][b] --
        {
            float2* rp = reinterpret_cast<float2*>(&red[kq * 384 + (bp << 1)]);
            rp[0 * 32] = a0; rp[1 * 32] = a1; rp[2 * 32] = a2;
            rp[3 * 32] = a3; rp[4 * 32] = a4; rp[5 * 32] = a5;
        }
        __syncthreads();

        // -- epilogue: (u, b) threads sum 8 k-slices, gate math, store h_t --
        if (tid < 128) {
            float s0 = ebias[0], s1 = ebias[1], s2 = ebias[2];
            #pragma unroll
            for (int q = 0; q < 8; q++) {
                const float* rq = &red[q * 384 + eb];
                s0 += rq[(0 * 2 + eu) * 64];
                s1 += rq[(1 * 2 + eu) * 64];
                s2 += rq[(2 * 2 + eu) * 64];
            }
            float r = 1.f / (1.f + __expf(-(xg0 + s0)));
            float z = 1.f / (1.f + __expf(-(xg1 + s1)));
            float nv = tanhf(xg2 + r * s2);
            float hn = (1.f - z) * nv + z * hprev;
            __stcg(hseq + ((size_t)t * Hn + 2 * p + eu) * Bn + eb, hn);
        }
        __syncthreads();

        // -- grid barrier: release arrive on monotonic counter, acquire spin --
        target += gridDim.x;
        if (tid == 0) {
            asm volatile("red.release.gpu.global.add.u32 [%0], 1;"
                         :: "l"(&g_bar_ctr) : "memory");
            unsigned v;
            do {
                asm volatile("ld.acquire.gpu.global.u32 %0, [%1];"
                             : "=r"(v) : "l"(&g_bar_ctr));
            } while (v < target);
        }
        __syncthreads();
    }
}

// ---------------- launch ----------------
extern "C" void kernel_launch(void* const* d_in, const int* in_sizes, int n_in,
                              void* d_out, int out_size) {
    const float* x     = (const float*)d_in[0];
    const float* W_ih0 = (const float*)d_in[1];
    const float* W_hh0 = (const float*)d_in[2];
    const float* b_ih0 = (const float*)d_in[3];
    const float* b_hh0 = (const float*)d_in[4];
    const float* W_ih1 = (const float*)d_in[5];
    const float* W_hh1 = (const float*)d_in[6];
    const float* b_ih1 = (const float*)d_in[7];
    const float* b_hh1 = (const float*)d_in[8];
    const float* fc_w  = (const float*)d_in[9];
    const float* fc_b  = (const float*)d_in[10];
    float* out = (float*)d_out;

    float* gates_ptr = nullptr;
    float* h_ptr = nullptr;
    unsigned* bar_ptr = nullptr;
    cudaGetSymbolAddress((void**)&gates_ptr, g_gates);
    cudaGetSymbolAddress((void**)&h_ptr, g_h);
    cudaGetSymbolAddress((void**)&bar_ptr, g_bar_ctr);

    // layer 0 input gates: [T][768][B] = x @ W_ih0^T + b_ih0
    gemm_k<0, 0><<<dim3(12, Tn), 256>>>(x, W_ih0, b_ih0, gates_ptr, In, G3);
    // layer 0 scan -> g_h
    cudaMemsetAsync(bar_ptr, 0, sizeof(unsigned));
    gru_scan<<<128, 256>>>(W_hh0, b_hh0, gates_ptr, h_ptr);
    // layer 1 input gates: g_h @ W_ih1^T + b_ih1
    gemm_k<1, 0><<<dim3(12, Tn), 256>>>(h_ptr, W_ih1, b_ih1, gates_ptr, Hn, G3);
    // layer 1 scan -> g_h (overwrites)
    cudaMemsetAsync(bar_ptr, 0, sizeof(unsigned));
    gru_scan<<<128, 256>>>(W_hh1, b_hh1, gates_ptr, h_ptr);
    // FC head: out[B][T][C] = g_h @ fc_w^T + fc_b
    gemm_k<1, 1><<<dim3(1, Tn), 256>>>(h_ptr, fc_w, fc_b, out, Hn, Cn);
}

// round 17
// speedup vs baseline: 2.4946x; 1.0067x over previous
#include <cuda_runtime.h>
#include <cuda_bf16.h>
#include <cstdint>
#include <cstddef>

#define Bn 64
#define Tn 2048
#define In 128
#define Hn 256
#define Cn 64
#define G3 768
#define SSTR 68

// ---------------- scratch ----------------
__device__ float g_gates[(size_t)Tn * G3 * Bn];   // [T][768][B]
__device__ float g_h[(size_t)Tn * Hn * Bn];       // [T][256][B]
__device__ unsigned g_bar_ctr;

// ---------------- tf32 helpers ----------------
__device__ __forceinline__ float to_tf32(float x) {
    float r;
    asm("cvt.rna.tf32.f32 %0, %1;" : "=f"(r) : "f"(x));
    return r;
}
__device__ __forceinline__ void mma_tf32(float* d, unsigned a0, unsigned a1,
                                         unsigned a2, unsigned a3,
                                         unsigned b0, unsigned b1) {
    asm volatile(
        "mma.sync.aligned.m16n8k8.row.col.f32.tf32.tf32.f32 "
        "{%0,%1,%2,%3}, {%4,%5,%6,%7}, {%8,%9}, {%0,%1,%2,%3};"
        : "+f"(d[0]), "+f"(d[1]), "+f"(d[2]), "+f"(d[3])
        : "r"(a0), "r"(a1), "r"(a2), "r"(a3), "r"(b0), "r"(b1));
}

// ---------------- tensor-core GEMM: C[t][n][b] = A @ W^T + bias ----------------
// grid (N/64, Tn), block 256. Full-K panel in smem (A[64][K+4], W[64][K+4]).
// A_MODE 0: A row-major [B][T][K];  A_MODE 1: A scratch [T][K][B].
// Output always scratch layout [T][N][B].
template<int A_MODE, int K>
__global__ void __launch_bounds__(256) gemm_tc(
    const float* __restrict__ A, const float* __restrict__ W,
    const float* __restrict__ bias, float* __restrict__ C, int N)
{
    constexpr int LD = K + 4;
    extern __shared__ float sm[];
    float* As = sm;                 // [64][LD]  (b-major)
    float* Ws = sm + 64 * LD;       // [64][LD]  (n-major)
    const int t   = blockIdx.y;
    const int bn  = blockIdx.x * 64;
    const int tid = threadIdx.x;

    // ---- fill A panel (tf32-converted) ----
    if (A_MODE == 0) {
        for (int i = tid; i < 64 * (K / 4); i += 256) {
            int b  = i / (K / 4);
            int kq = (i % (K / 4)) * 4;
            float4 v = *reinterpret_cast<const float4*>(
                A + ((size_t)b * Tn + t) * K + kq);
            v.x = to_tf32(v.x); v.y = to_tf32(v.y);
            v.z = to_tf32(v.z); v.w = to_tf32(v.w);
            *reinterpret_cast<float4*>(&As[b * LD + kq]) = v;
        }
    } else {
        for (int i = tid; i < 16 * K; i += 256) {
            int k  = i >> 4;
            int b4 = (i & 15) << 2;
            float4 v = *reinterpret_cast<const float4*>(
                A + ((size_t)t * K + k) * Bn + b4);
            As[(b4 + 0) * LD + k] = to_tf32(v.x);
            As[(b4 + 1) * LD + k] = to_tf32(v.y);
            As[(b4 + 2) * LD + k] = to_tf32(v.z);
            As[(b4 + 3) * LD + k] = to_tf32(v.w);
        }
    }
    // ---- fill W panel ----
    for (int i = tid; i < 64 * (K / 4); i += 256) {
        int nn = i / (K / 4);
        int kq = (i % (K / 4)) * 4;
        float4 v = *reinterpret_cast<const float4*>(
            W + (size_t)(bn + nn) * K + kq);
        v.x = to_tf32(v.x); v.y = to_tf32(v.y);
        v.z = to_tf32(v.z); v.w = to_tf32(v.w);
        *reinterpret_cast<float4*>(&Ws[nn * LD + kq]) = v;
    }
    __syncthreads();

    // ---- mma: warp (wm, wn) covers m16 rows [16wm,16wm+16) x n32 cols ----
    const int wid  = tid >> 5, lane = tid & 31;
    const int g    = lane >> 2, t4 = lane & 3;
    const int wm   = wid & 3, wn = wid >> 2;
    const int r0   = 16 * wm + g;
    const unsigned* Au = reinterpret_cast<const unsigned*>(As);
    const unsigned* Wu = reinterpret_cast<const unsigned*>(Ws);

    float acc[4][4] = {};
    #pragma unroll
    for (int k8 = 0; k8 < K; k8 += 8) {
        unsigned a0 = Au[(r0 + 0) * LD + k8 + t4];
        unsigned a1 = Au[(r0 + 8) * LD + k8 + t4];
        unsigned a2 = Au[(r0 + 0) * LD + k8 + t4 + 4];
        unsigned a3 = Au[(r0 + 8) * LD + k8 + t4 + 4];
        #pragma unroll
        for (int nt = 0; nt < 4; nt++) {
            int n = 32 * wn + 8 * nt + g;
            unsigned b0 = Wu[n * LD + k8 + t4];
            unsigned b1 = Wu[n * LD + k8 + t4 + 4];
            mma_tf32(acc[nt], a0, a1, a2, a3, b0, b1);
        }
    }

    // ---- epilogue: D[b][n] -> C[(t*N + n)*64 + b] ----
    #pragma unroll
    for (int nt = 0; nt < 4; nt++) {
        int n  = bn + 32 * wn + 8 * nt + 2 * t4;
        int b0 = 16 * wm + g;
        float bv0 = bias[n], bv1 = bias[n + 1];
        C[((size_t)t * N + n    ) * Bn + b0    ] = acc[nt][0] + bv0;
        C[((size_t)t * N + n + 1) * Bn + b0    ] = acc[nt][1] + bv1;
        C[((size_t)t * N + n    ) * Bn + b0 + 8] = acc[nt][2] + bv0;
        C[((size_t)t * N + n + 1) * Bn + b0 + 8] = acc[nt][3] + bv1;
    }
}

// ---------------- fp32 GEMM (FC head only): out[B][T][C] ----------------
__global__ void __launch_bounds__(256) gemm_fc(
    const float* __restrict__ A, const float* __restrict__ W,
    const float* __restrict__ bias, float* __restrict__ C)
{
    __shared__ float As[16 * SSTR];
    __shared__ float Ws[16 * SSTR];
    const int t   = blockIdx.y;
    const int tid = threadIdx.x;
    const int tx  = tid & 15;
    const int ty  = tid >> 4;
    const int K = Hn, N = Cn;
    float acc[4][4] = {};

    for (int k0 = 0; k0 < K; k0 += 16) {
        {
            int b4 = (tid & 15) << 2, kk = tid >> 4;
            const float4 v = *reinterpret_cast<const float4*>(
                A + ((size_t)t * K + k0 + kk) * Bn + b4);
            As[kk * SSTR + b4 + 0] = v.x;
            As[kk * SSTR + b4 + 1] = v.y;
            As[kk * SSTR + b4 + 2] = v.z;
            As[kk * SSTR + b4 + 3] = v.w;
        }
        {
            int nn = tid & 63, kq = (tid >> 6) << 2;
            const float4 v = *reinterpret_cast<const float4*>(
                W + (size_t)nn * K + k0 + kq);
            Ws[(kq + 0) * SSTR + nn] = v.x;
            Ws[(kq + 1) * SSTR + nn] = v.y;
            Ws[(kq + 2) * SSTR + nn] = v.z;
            Ws[(kq + 3) * SSTR + nn] = v.w;
        }
        __syncthreads();
        #pragma unroll
        for (int k = 0; k < 16; k++) {
            float4 a = *reinterpret_cast<const float4*>(&As[k * SSTR + (ty << 2)]);
            float4 w = *reinterpret_cast<const float4*>(&Ws[k * SSTR + (tx << 2)]);
            acc[0][0] = fmaf(a.x, w.x, acc[0][0]);
            acc[0][1] = fmaf(a.x, w.y, acc[0][1]);
            acc[0][2] = fmaf(a.x, w.z, acc[0][2]);
            acc[0][3] = fmaf(a.x, w.w, acc[0][3]);
            acc[1][0] = fmaf(a.y, w.x, acc[1][0]);
            acc[1][1] = fmaf(a.y, w.y, acc[1][1]);
            acc[1][2] = fmaf(a.y, w.z, acc[1][2]);
            acc[1][3] = fmaf(a.y, w.w, acc[1][3]);
            acc[2][0] = fmaf(a.z, w.x, acc[2][0]);
            acc[2][1] = fmaf(a.z, w.y, acc[2][1]);
            acc[2][2] = fmaf(a.z, w.z, acc[2][2]);
            acc[2][3] = fmaf(a.z, w.w, acc[2][3]);
            acc[3][0] = fmaf(a.w, w.x, acc[3][0]);
            acc[3][1] = fmaf(a.w, w.y, acc[3][1]);
            acc[3][2] = fmaf(a.w, w.z, acc[3][2]);
            acc[3][3] = fmaf(a.w, w.w, acc[3][3]);
        }
        __syncthreads();
    }
    #pragma unroll
    for (int i = 0; i < 4; i++) {
        int bb = (ty << 2) + i;
        float4 o = make_float4(acc[i][0] + bias[(tx << 2) + 0],
                               acc[i][1] + bias[(tx << 2) + 1],
                               acc[i][2] + bias[(tx << 2) + 2],
                               acc[i][3] + bias[(tx << 2) + 3]);
        *reinterpret_cast<float4*>(C + ((size_t)bb * Tn + t) * Cn + (tx << 2)) = o;
    }
}

// ---------------- GRU recurrent scan (unchanged from R13) ----------------
__global__ void __launch_bounds__(256, 1) gru_scan(
    const float* __restrict__ W_hh, const float* __restrict__ b_hh,
    const float* __restrict__ gates, float* __restrict__ hseq)
{
    __shared__ float Ws[6 * 256];
    __shared__ float red[8 * 6 * 64];
    const int tid = threadIdx.x;
    const int bp  = tid & 31;
    const int kq  = tid >> 5;
    const int p   = blockIdx.x;
    const int k0  = kq << 5;

    for (int i = tid; i < 6 * 256; i += 256) {
        int j = i >> 8, k = i & 255;
        Ws[i] = W_hh[((size_t)((j >> 1) * Hn) + (2 * p + (j & 1))) * Hn + k];
    }
    const int eu = tid >> 6, eb = tid & 63;
    float ebias[3];
    if (tid < 128) {
        #pragma unroll
        for (int g = 0; g < 3; g++)
            ebias[g] = b_hh[g * Hn + 2 * p + eu];
    }
    __syncthreads();

    unsigned target = 0;
    for (int t = 0; t < Tn; t++) {
        float xg0 = 0.f, xg1 = 0.f, xg2 = 0.f, hprev = 0.f;
        if (tid < 128) {
            const float* gp = gates + (size_t)t * G3 * Bn
                              + (size_t)(2 * p + eu) * Bn + eb;
            xg0 = __ldg(gp);
            xg1 = __ldg(gp + (size_t)Hn * Bn);
            xg2 = __ldg(gp + (size_t)2 * Hn * Bn);
            if (t > 0)
                hprev = __ldcg(hseq + ((size_t)(t - 1) * Hn + 2 * p + eu) * Bn + eb);
        }

        float2 a0 = {0.f, 0.f}, a1 = a0, a2 = a0, a3 = a0, a4 = a0, a5 = a0;
        if (t > 0) {
            const float* hp = hseq + ((size_t)(t - 1) * Hn + k0) * Bn + (bp << 1);
            #pragma unroll
            for (int kk = 0; kk < 32; kk += 4) {
                float2 h0 = __ldcg(reinterpret_cast<const float2*>(hp + (size_t)(kk + 0) * Bn));
                float2 h1 = __ldcg(reinterpret_cast<const float2*>(hp + (size_t)(kk + 1) * Bn));
                float2 h2 = __ldcg(reinterpret_cast<const float2*>(hp + (size_t)(kk + 2) * Bn));
                float2 h3 = __ldcg(reinterpret_cast<const float2*>(hp + (size_t)(kk + 3) * Bn));
                float4 w0 = *reinterpret_cast<const float4*>(&Ws[0 * 256 + k0 + kk]);
                float4 w1 = *reinterpret_cast<const float4*>(&Ws[1 * 256 + k0 + kk]);
                float4 w2 = *reinterpret_cast<const float4*>(&Ws[2 * 256 + k0 + kk]);
                float4 w3 = *reinterpret_cast<const float4*>(&Ws[3 * 256 + k0 + kk]);
                float4 w4 = *reinterpret_cast<const float4*>(&Ws[4 * 256 + k0 + kk]);
                float4 w5 = *reinterpret_cast<const float4*>(&Ws[5 * 256 + k0 + kk]);
                a0.x = fmaf(w0.x, h0.x, a0.x); a0.y = fmaf(w0.x, h0.y, a0.y);
                a1.x = fmaf(w1.x, h0.x, a1.x); a1.y = fmaf(w1.x, h0.y, a1.y);
                a2.x = fmaf(w2.x, h0.x, a2.x); a2.y = fmaf(w2.x, h0.y, a2.y);
                a3.x = fmaf(w3.x, h0.x, a3.x); a3.y = fmaf(w3.x, h0.y, a3.y);
                a4.x = fmaf(w4.x, h0.x, a4.x); a4.y = fmaf(w4.x, h0.y, a4.y);
                a5.x = fmaf(w5.x, h0.x, a5.x); a5.y = fmaf(w5.x, h0.y, a5.y);
                a0.x = fmaf(w0.y, h1.x, a0.x); a0.y = fmaf(w0.y, h1.y, a0.y);
                a1.x = fmaf(w1.y, h1.x, a1.x); a1.y = fmaf(w1.y, h1.y, a1.y);
                a2.x = fmaf(w2.y, h1.x, a2.x); a2.y = fmaf(w2.y, h1.y, a2.y);
                a3.x = fmaf(w3.y, h1.x, a3.x); a3.y = fmaf(w3.y, h1.y, a3.y);
                a4.x = fmaf(w4.y, h1.x, a4.x); a4.y = fmaf(w4.y, h1.y, a4.y);
                a5.x = fmaf(w5.y, h1.x, a5.x); a5.y = fmaf(w5.y, h1.y, a5.y);
                a0.x = fmaf(w0.z, h2.x, a0.x); a0.y = fmaf(w0.z, h2.y, a0.y);
                a1.x = fmaf(w1.z, h2.x, a1.x); a1.y = fmaf(w1.z, h2.y, a1.y);
                a2.x = fmaf(w2.z, h2.x, a2.x); a2.y = fmaf(w2.z, h2.y, a2.y);
                a3.x = fmaf(w3.z, h2.x, a3.x); a3.y = fmaf(w3.z, h2.y, a3.y);
                a4.x = fmaf(w4.z, h2.x, a4.x); a4.y = fmaf(w4.z, h2.y, a4.y);
                a5.x = fmaf(w5.z, h2.x, a5.x); a5.y = fmaf(w5.z, h2.y, a5.y);
                a0.x = fmaf(w0.w, h3.x, a0.x); a0.y = fmaf(w0.w, h3.y, a0.y);
                a1.x = fmaf(w1.w, h3.x, a1.x); a1.y = fmaf(w1.w, h3.y, a1.y);
                a2.x = fmaf(w2.w, h3.x, a2.x); a2.y = fmaf(w2.w, h3.y, a2.y);
                a3.x = fmaf(w3.w, h3.x, a3.x); a3.y = fmaf(w3.w, h3.y, a3.y);
                a4.x = fmaf(w4.w, h3.x, a4.x); a4.y = fmaf(w4.w, h3.y, a4.y);
                a5.x = fmaf(w5.w, h3.x, a5.x); a5.y = fmaf(w5.w, h3.y, a5.y);
            }
        }

        {
            float2* rp = reinterpret_cast<float2*>(&red[kq * 384 + (bp << 1)]);
            rp[0 * 32] = a0; rp[1 * 32] = a1; rp[2 * 32] = a2;
            rp[3 * 32] = a3; rp[4 * 32] = a4; rp[5 * 32] = a5;
        }
        __syncthreads();

        if (tid < 128) {
            float s0 = ebias[0], s1 = ebias[1], s2 = ebias[2];
            #pragma unroll
            for (int q = 0; q < 8; q++) {
                const float* rq = &red[q * 384 + eb];
                s0 += rq[(0 * 2 + eu) * 64];
                s1 += rq[(1 * 2 + eu) * 64];
                s2 += rq[(2 * 2 + eu) * 64];
            }
            float r = 1.f / (1.f + __expf(-(xg0 + s0)));
            float z = 1.f / (1.f + __expf(-(xg1 + s1)));
            float nv = tanhf(xg2 + r * s2);
            float hn = (1.f - z) * nv + z * hprev;
            __stcg(hseq + ((size_t)t * Hn + 2 * p + eu) * Bn + eb, hn);
        }
        __syncthreads();

        target += gridDim.x;
        if (tid == 0) {
            asm volatile("red.release.gpu.global.add.u32 [%0], 1;"
                         :: "l"(&g_bar_ctr) : "memory");
            unsigned v;
            do {
                asm volatile("ld.acquire.gpu.global.u32 %0, [%1];"
                             : "=r"(v) : "l"(&g_bar_ctr));
            } while (v < target);
        }
        __syncthreads();
    }
}

// ---------------- launch ----------------
extern "C" void kernel_launch(void* const* d_in, const int* in_sizes, int n_in,
                              void* d_out, int out_size) {
    const float* x     = (const float*)d_in[0];
    const float* W_ih0 = (const float*)d_in[1];
    const float* W_hh0 = (const float*)d_in[2];
    const float* b_ih0 = (const float*)d_in[3];
    const float* b_hh0 = (const float*)d_in[4];
    const float* W_ih1 = (const float*)d_in[5];
    const float* W_hh1 = (const float*)d_in[6];
    const float* b_ih1 = (const float*)d_in[7];
    const float* b_hh1 = (const float*)d_in[8];
    const float* fc_w  = (const float*)d_in[9];
    const float* fc_b  = (const float*)d_in[10];
    float* out = (float*)d_out;

    float* gates_ptr = nullptr;
    float* h_ptr = nullptr;
    unsigned* bar_ptr = nullptr;
    cudaGetSymbolAddress((void**)&gates_ptr, g_gates);
    cudaGetSymbolAddress((void**)&h_ptr, g_h);
    cudaGetSymbolAddress((void**)&bar_ptr, g_bar_ctr);

    const int smem0 = 2 * 64 * (In + 4) * (int)sizeof(float);   // 67584 B
    const int smem1 = 2 * 64 * (Hn + 4) * (int)sizeof(float);   // 133120 B
    cudaFuncSetAttribute(gemm_tc<0, In>, cudaFuncAttributeMaxDynamicSharedMemorySize, smem0);
    cudaFuncSetAttribute(gemm_tc<1, Hn>, cudaFuncAttributeMaxDynamicSharedMemorySize, smem1);

    // layer 0 input gates (tf32 tensor cores)
    gemm_tc<0, In><<<dim3(12, Tn), 256, smem0>>>(x, W_ih0, b_ih0, gates_ptr, G3);
    // layer 0 scan
    cudaMemsetAsync(bar_ptr, 0, sizeof(unsigned));
    gru_scan<<<128, 256>>>(W_hh0, b_hh0, gates_ptr, h_ptr);
    // layer 1 input gates (tf32 tensor cores)
    gemm_tc<1, Hn><<<dim3(12, Tn), 256, smem1>>>(h_ptr, W_ih1, b_ih1, gates_ptr, G3);
    // layer 1 scan
    cudaMemsetAsync(bar_ptr, 0, sizeof(unsigned));
    gru_scan<<<128, 256>>>(W_hh1, b_hh1, gates_ptr, h_ptr);
    // FC head (fp32 for output precision)
    gemm_fc<<<dim3(1, Tn), 256>>>(h_ptr, fc_w, fc_b, out);
}